// round 8
// baseline (speedup 1.0000x reference)
#include <cuda_runtime.h>
#include <cuda_bf16.h>

// Problem constants (fixed by the dataset)
#define F_IN 100
#define F_HID 100
#define F_EMB 64
#define N_CLS 40
#define NN   50000
#define EE   800000
#define CAP  96        // fixed slots per node; P(deg>=96) ~ 0 for Poisson(16)
#define PAD  128       // padded row stride (floats) for 100-wide activations

// ---------------- scratch (no allocations allowed) ----------------
__device__ float g_A[NN * PAD];        // lin outputs (scaled by dinv), padded rows
__device__ float g_B[NN * PAD];        // aggregated hidden, padded rows
__device__ int   g_cnt[NN];            // cursor -> degree
__device__ int   g_col[NN * CAP];      // slot CSR (CAP multiple of 4 -> int4 aligned)
__device__ float g_dinv[NN];

// ---------------- f32x2 packed helpers (sm_103a) ----------------
__device__ __forceinline__ unsigned long long pack2(float lo, float hi) {
    unsigned long long r;
    asm("mov.b64 %0, {%1, %2};" : "=l"(r) : "f"(lo), "f"(hi));
    return r;
}
__device__ __forceinline__ void ffma2(unsigned long long& d,
                                      unsigned long long a,
                                      unsigned long long b) {
    asm("fma.rn.f32x2 %0, %1, %2, %3;" : "=l"(d) : "l"(a), "l"(b), "l"(d));
}
__device__ __forceinline__ float2 unpack2(unsigned long long v) {
    float lo, hi;
    asm("mov.b64 {%0, %1}, %2;" : "=f"(lo), "=f"(hi) : "l"(v));
    return make_float2(lo, hi);
}

// ---------------- slot-CSR build ----------------
// cursor (g_cnt) is zeroed by cudaMemsetAsync before this kernel.
__global__ void fill_kernel(const int* __restrict__ src, const int* __restrict__ dst, int e) {
    int i = (blockIdx.x * blockDim.x + threadIdx.x) * 4;
    if (i + 3 < e) {
        int4 d4 = *(const int4*)(dst + i);
        int4 s4 = *(const int4*)(src + i);
        int p0 = atomicAdd(&g_cnt[d4.x], 1);
        int p1 = atomicAdd(&g_cnt[d4.y], 1);
        int p2 = atomicAdd(&g_cnt[d4.z], 1);
        int p3 = atomicAdd(&g_cnt[d4.w], 1);
        if (p0 < CAP) g_col[d4.x * CAP + p0] = s4.x;
        if (p1 < CAP) g_col[d4.y * CAP + p1] = s4.y;
        if (p2 < CAP) g_col[d4.z * CAP + p2] = s4.z;
        if (p3 < CAP) g_col[d4.w * CAP + p3] = s4.w;
    } else {
        for (; i < e; ++i) {
            int d = dst[i];
            int p = atomicAdd(&g_cnt[d], 1);
            if (p < CAP) g_col[d * CAP + p] = src[i];
        }
    }
}

__global__ void dinv_kernel(int n) {
    int i = blockIdx.x * blockDim.x + threadIdx.x;
    if (i < n) g_dinv[i] = rsqrtf((float)(g_cnt[i] + 1));   // +1 self loop
}

// ---------------- tiled fp32 GEMM with f32x2 packed FMA ----------------
// out[n, NOUT (stride OUTS)] = in[n, K (stride INS)] @ W[K, NOUT]
// BM=128, BK=32. x tile stored TRANSPOSED (xs[k][row]) so each k-step loads
// 16 rows as 4x LDS.128 whose 64-bit halves ARE the row-pair f32x2 operands.
template<int K, int NOUT, int NP, int INS, int OUTS, bool SCALE, bool BIAS>
__global__ void __launch_bounds__(256) gemm_kernel(const float* __restrict__ in,
                                                   const float* __restrict__ W,
                                                   const float* __restrict__ bias,
                                                   const float* __restrict__ dinv,
                                                   float* __restrict__ out, int n) {
    constexpr int BM = 128, BK = 32, NJ = NP / 32;
    __shared__ float xs[BK][BM + 4];
    __shared__ float ws[BK][NP];
    const int tid = threadIdx.x;
    const int tx = tid & 31, ty = tid >> 5;      // 8 warps, 16 rows each
    const int rbase = blockIdx.x * BM;

    unsigned long long acc2[8][NJ];              // row-pairs x cols
#pragma unroll
    for (int p = 0; p < 8; ++p)
#pragma unroll
        for (int j = 0; j < NJ; ++j) acc2[p][j] = 0ull;

    for (int kc = 0; kc < K; kc += BK) {
        // x tile: 128 rows x 32 k, 2 threads/row, stored transposed
        {
            int row  = tid >> 1;
            int q    = tid & 1;
            int grow = rbase + row;
#pragma unroll
            for (int h = 0; h < 4; ++h) {
                int c  = q * 16 + h * 4;
                int gk = kc + c;
                float4 xv = make_float4(0.f, 0.f, 0.f, 0.f);
                if (grow < n && gk < K)   // K % 4 == 0 so gk<K implies gk+3<K
                    xv = *(const float4*)(in + (size_t)grow * INS + gk);
                xs[c + 0][row] = xv.x;
                xs[c + 1][row] = xv.y;
                xs[c + 2][row] = xv.z;
                xs[c + 3][row] = xv.w;
            }
        }
        // W tile (zero padded)
        for (int i = tid; i < BK * NP; i += 256) {
            int kk = i / NP;
            int c  = i - kk * NP;
            int gkk = kc + kk;
            float w = 0.f;
            if (gkk < K && c < NOUT) w = W[gkk * NOUT + c];
            ws[kk][c] = w;
        }
        __syncthreads();
#pragma unroll
        for (int k = 0; k < BK; ++k) {
            const ulonglong2* pa = (const ulonglong2*)&xs[k][ty * 16];
            ulonglong2 v0 = pa[0], v1 = pa[1], v2 = pa[2], v3 = pa[3];
            unsigned long long a[8] = {v0.x, v0.y, v1.x, v1.y, v2.x, v2.y, v3.x, v3.y};
#pragma unroll
            for (int j = 0; j < NJ; ++j) {
                float w = ws[k][tx + 32 * j];
                unsigned long long wd = pack2(w, w);
#pragma unroll
                for (int p = 0; p < 8; ++p) ffma2(acc2[p][j], a[p], wd);
            }
        }
        __syncthreads();
    }
    // epilogue: unpack row pairs
#pragma unroll
    for (int p = 0; p < 8; ++p) {
        int r0 = rbase + ty * 16 + 2 * p;
        int r1 = r0 + 1;
        float dv0 = 1.f, dv1 = 1.f;
        if (SCALE) {
            if (r0 < n) dv0 = dinv[r0];
            if (r1 < n) dv1 = dinv[r1];
        }
#pragma unroll
        for (int j = 0; j < NJ; ++j) {
            int c = tx + 32 * j;
            if (c < NOUT) {
                float2 v = unpack2(acc2[p][j]);
                float b = BIAS ? bias[c] : 0.f;
                if (r0 < n) out[(size_t)r0 * OUTS + c] = v.x * dv0 + b;
                if (r1 < n) out[(size_t)r1 * OUTS + c] = v.y * dv1 + b;
            }
        }
    }
}

// ---------------- warp-per-node gather (F=100, padded rows of 32 float4) ----------
// out[d] = relu( dinv[d] * ( A[d] + sum_src A[src] ) + bias ), row stride PAD.
// Rows are 512B-aligned -> every gather touches exactly 4 cache lines.
__global__ void __launch_bounds__(256) agg100_kernel(const float* __restrict__ A,
                                                     const float* __restrict__ bias,
                                                     float* __restrict__ out, int n) {
    constexpr int RS = PAD / 4;                  // 32 float4 per row
    const int node = (blockIdx.x * blockDim.x + threadIdx.x) >> 5;
    const int lane = threadIdx.x & 31;
    if (node >= n) return;
    const bool act = lane < 25;
    const float4* __restrict__ base = (const float4*)A;
    const size_t rowoff = (size_t)node * RS;

    float4 acc = make_float4(0.f, 0.f, 0.f, 0.f);
    if (act) acc = base[rowoff + lane];          // self loop term

    int deg = g_cnt[node]; if (deg > CAP) deg = CAP;
    const int4* __restrict__ colp = (const int4*)(g_col + node * CAP);
    const int nb4 = deg >> 2;
    int b = 0;
    for (; b + 2 <= nb4; b += 2) {               // 8 gathers in flight
        int4 i0 = colp[b];
        int4 i1 = colp[b + 1];
        if (act) {
            float4 v0 = base[(size_t)i0.x * RS + lane];
            float4 v1 = base[(size_t)i0.y * RS + lane];
            float4 v2 = base[(size_t)i0.z * RS + lane];
            float4 v3 = base[(size_t)i0.w * RS + lane];
            float4 v4 = base[(size_t)i1.x * RS + lane];
            float4 v5 = base[(size_t)i1.y * RS + lane];
            float4 v6 = base[(size_t)i1.z * RS + lane];
            float4 v7 = base[(size_t)i1.w * RS + lane];
            acc.x += ((v0.x + v1.x) + (v2.x + v3.x)) + ((v4.x + v5.x) + (v6.x + v7.x));
            acc.y += ((v0.y + v1.y) + (v2.y + v3.y)) + ((v4.y + v5.y) + (v6.y + v7.y));
            acc.z += ((v0.z + v1.z) + (v2.z + v3.z)) + ((v4.z + v5.z) + (v6.z + v7.z));
            acc.w += ((v0.w + v1.w) + (v2.w + v3.w)) + ((v4.w + v5.w) + (v6.w + v7.w));
        }
    }
    for (; b < nb4; ++b) {
        int4 i0 = colp[b];
        if (act) {
            float4 v0 = base[(size_t)i0.x * RS + lane];
            float4 v1 = base[(size_t)i0.y * RS + lane];
            float4 v2 = base[(size_t)i0.z * RS + lane];
            float4 v3 = base[(size_t)i0.w * RS + lane];
            acc.x += (v0.x + v1.x) + (v2.x + v3.x);
            acc.y += (v0.y + v1.y) + (v2.y + v3.y);
            acc.z += (v0.z + v1.z) + (v2.z + v3.z);
            acc.w += (v0.w + v1.w) + (v2.w + v3.w);
        }
    }
    for (int e = nb4 * 4; e < deg; ++e) {
        int s = g_col[node * CAP + e];
        if (act) {
            float4 v = base[(size_t)s * RS + lane];
            acc.x += v.x; acc.y += v.y; acc.z += v.z; acc.w += v.w;
        }
    }
    if (act) {
        float dv = g_dinv[node];
        float4 bv = ((const float4*)bias)[lane];
        float4 r;
        r.x = fmaxf(fmaf(acc.x, dv, bv.x), 0.f);
        r.y = fmaxf(fmaf(acc.y, dv, bv.y), 0.f);
        r.z = fmaxf(fmaf(acc.z, dv, bv.z), 0.f);
        r.w = fmaxf(fmaf(acc.w, dv, bv.w), 0.f);
        ((float4*)out)[rowoff + lane] = r;
    }
}

// ---------------- half-warp-per-node gather (F=64: 16 lanes, 2 nodes/warp) ----
__global__ void __launch_bounds__(256) agg64_kernel(const float* __restrict__ A,
                                                    const float* __restrict__ bias,
                                                    float* __restrict__ out, int n) {
    constexpr int NV4 = 16;
    const int gwarp = (blockIdx.x * blockDim.x + threadIdx.x) >> 5;
    const int lane  = threadIdx.x & 31;
    const int node  = gwarp * 2 + (lane >> 4);
    const int sub   = lane & 15;
    if (node >= n) return;
    const float4* __restrict__ base = (const float4*)A;
    const size_t rowoff = (size_t)node * NV4;

    float4 acc = base[rowoff + sub];             // self loop term

    int deg = g_cnt[node]; if (deg > CAP) deg = CAP;
    const int4* __restrict__ colp = (const int4*)(g_col + node * CAP);
    const int nb4 = deg >> 2;
    int b = 0;
    for (; b + 2 <= nb4; b += 2) {
        int4 i0 = colp[b];
        int4 i1 = colp[b + 1];
        float4 v0 = base[(size_t)i0.x * NV4 + sub];
        float4 v1 = base[(size_t)i0.y * NV4 + sub];
        float4 v2 = base[(size_t)i0.z * NV4 + sub];
        float4 v3 = base[(size_t)i0.w * NV4 + sub];
        float4 v4 = base[(size_t)i1.x * NV4 + sub];
        float4 v5 = base[(size_t)i1.y * NV4 + sub];
        float4 v6 = base[(size_t)i1.z * NV4 + sub];
        float4 v7 = base[(size_t)i1.w * NV4 + sub];
        acc.x += ((v0.x + v1.x) + (v2.x + v3.x)) + ((v4.x + v5.x) + (v6.x + v7.x));
        acc.y += ((v0.y + v1.y) + (v2.y + v3.y)) + ((v4.y + v5.y) + (v6.y + v7.y));
        acc.z += ((v0.z + v1.z) + (v2.z + v3.z)) + ((v4.z + v5.z) + (v6.z + v7.z));
        acc.w += ((v0.w + v1.w) + (v2.w + v3.w)) + ((v4.w + v5.w) + (v6.w + v7.w));
    }
    for (; b < nb4; ++b) {
        int4 i0 = colp[b];
        float4 v0 = base[(size_t)i0.x * NV4 + sub];
        float4 v1 = base[(size_t)i0.y * NV4 + sub];
        float4 v2 = base[(size_t)i0.z * NV4 + sub];
        float4 v3 = base[(size_t)i0.w * NV4 + sub];
        acc.x += (v0.x + v1.x) + (v2.x + v3.x);
        acc.y += (v0.y + v1.y) + (v2.y + v3.y);
        acc.z += (v0.z + v1.z) + (v2.z + v3.z);
        acc.w += (v0.w + v1.w) + (v2.w + v3.w);
    }
    for (int e = nb4 * 4; e < deg; ++e) {
        int s = g_col[node * CAP + e];
        float4 v = base[(size_t)s * NV4 + sub];
        acc.x += v.x; acc.y += v.y; acc.z += v.z; acc.w += v.w;
    }
    {
        float dv = g_dinv[node];
        float4 bv = ((const float4*)bias)[sub];
        float4 r;
        r.x = fmaxf(fmaf(acc.x, dv, bv.x), 0.f);
        r.y = fmaxf(fmaf(acc.y, dv, bv.y), 0.f);
        r.z = fmaxf(fmaf(acc.z, dv, bv.z), 0.f);
        r.w = fmaxf(fmaf(acc.w, dv, bv.w), 0.f);
        ((float4*)out)[rowoff + sub] = r;
    }
}

// ---------------- host launcher ----------------
extern "C" void kernel_launch(void* const* d_in, const int* in_sizes, int n_in,
                              void* d_out, int out_size) {
    const float* x    = (const float*)d_in[0];
    const int*   eidx = (const int*)d_in[1];
    const float* W1   = (const float*)d_in[2];
    const float* b1   = (const float*)d_in[3];
    const float* W2   = (const float*)d_in[4];
    const float* b2   = (const float*)d_in[5];
    const float* Wc   = (const float*)d_in[6];
    const float* bc   = (const float*)d_in[7];
    float* out = (float*)d_out;

    const int n = in_sizes[0] / F_IN;       // 50000
    const int e = in_sizes[1] / 2;          // 800000
    const int* src = eidx;
    const int* dst = eidx + e;

    // Device symbols must be resolved to device addresses before being passed
    // as kernel arguments (host shadow is ATS-dereferenceable on GB300 -> zeros).
    float* gA;    cudaGetSymbolAddress((void**)&gA,    g_A);
    float* gB;    cudaGetSymbolAddress((void**)&gB,    g_B);
    float* gDinv; cudaGetSymbolAddress((void**)&gDinv, g_dinv);
    int*   gCnt;  cudaGetSymbolAddress((void**)&gCnt,  g_cnt);

    const int TB = 256;
    // slot-CSR build: memset cursor, bucket fill (ILP4), dinv from degree
    cudaMemsetAsync(gCnt, 0, n * sizeof(int));
    fill_kernel<<<((e + 3) / 4 + TB - 1) / TB, TB>>>(src, dst, e);
    dinv_kernel<<<(n + TB - 1) / TB, TB>>>(n);

    const int gemm_blocks   = (n + 127) / 128;
    const int agg100_blocks = (n + 7) / 8;       // warp per node
    const int agg64_blocks  = (n + 15) / 16;     // 2 nodes per warp

    // layer 1: A = dinv * (x @ W1)  [padded stride 128]
    gemm_kernel<F_IN, F_HID, 128, F_IN, PAD, true, false>
        <<<gemm_blocks, 256>>>(x, W1, nullptr, gDinv, gA, n);
    // B = relu(dinv*(A[d]+sum A[src]) + b1)  [padded stride 128]
    agg100_kernel<<<agg100_blocks, 256>>>(gA, b1, gB, n);

    // layer 2: A = dinv * (B @ W2)  [stride 64]
    gemm_kernel<F_HID, F_EMB, 64, PAD, F_EMB, true, false>
        <<<gemm_blocks, 256>>>(gB, W2, nullptr, gDinv, gA, n);
    agg64_kernel<<<agg64_blocks, 256>>>(gA, b2, gB, n);

    // classifier: out = B @ Wc + bc
    gemm_kernel<F_EMB, N_CLS, 64, F_EMB, N_CLS, false, true>
        <<<gemm_blocks, 256>>>(gB, Wc, bc, nullptr, out, n);
}

// round 9
// speedup vs baseline: 1.0848x; 1.0848x over previous
#include <cuda_runtime.h>
#include <cuda_fp16.h>

// Problem constants (fixed by the dataset)
#define F_IN 100
#define F_HID 100
#define F_EMB 64
#define N_CLS 40
#define NN   50000
#define EE   800000
#define CAP  96        // fixed slots per node; P(deg>=96) ~ 0 for Poisson(16)
#define PADH 128       // padded fp16 row stride for 100-wide activations (256B)

// ---------------- scratch (no allocations allowed) ----------------
__device__ __half g_Ah1[NN * PADH];    // layer1 lin output, fp16, dinv-scaled, padded
__device__ __half g_Ah2[NN * F_EMB];   // layer2 lin output, fp16, dinv-scaled (128B rows)
__device__ float  g_B1[NN * F_HID];    // layer1 agg output (fp32, stride 100)
__device__ float  g_B2[NN * F_EMB];    // layer2 agg output (fp32, stride 64)
__device__ int    g_cnt[NN];           // cursor -> degree
__device__ int    g_col[NN * CAP];     // slot CSR (CAP multiple of 4 -> int4 aligned)
__device__ float  g_dinv[NN];

// ---------------- f32x2 packed helpers (sm_103a) ----------------
__device__ __forceinline__ unsigned long long pack2(float lo, float hi) {
    unsigned long long r;
    asm("mov.b64 %0, {%1, %2};" : "=l"(r) : "f"(lo), "f"(hi));
    return r;
}
__device__ __forceinline__ void ffma2(unsigned long long& d,
                                      unsigned long long a,
                                      unsigned long long b) {
    asm("fma.rn.f32x2 %0, %1, %2, %3;" : "=l"(d) : "l"(a), "l"(b), "l"(d));
}
__device__ __forceinline__ float2 unpack2(unsigned long long v) {
    float lo, hi;
    asm("mov.b64 {%0, %1}, %2;" : "=f"(lo), "=f"(hi) : "l"(v));
    return make_float2(lo, hi);
}

// convert 8 packed halves (uint4) to floats and add into acc[8]
__device__ __forceinline__ void h8_add(uint4 v, float* acc) {
    float2 f0 = __half22float2(*(const __half2*)&v.x);
    float2 f1 = __half22float2(*(const __half2*)&v.y);
    float2 f2 = __half22float2(*(const __half2*)&v.z);
    float2 f3 = __half22float2(*(const __half2*)&v.w);
    acc[0] += f0.x; acc[1] += f0.y; acc[2] += f1.x; acc[3] += f1.y;
    acc[4] += f2.x; acc[5] += f2.y; acc[6] += f3.x; acc[7] += f3.y;
}

// ---------------- slot-CSR build ----------------
// cursor (g_cnt) is zeroed by cudaMemsetAsync before this kernel.
__global__ void fill_kernel(const int* __restrict__ src, const int* __restrict__ dst, int e) {
    int i = (blockIdx.x * blockDim.x + threadIdx.x) * 4;
    if (i + 3 < e) {
        int4 d4 = *(const int4*)(dst + i);
        int4 s4 = *(const int4*)(src + i);
        int p0 = atomicAdd(&g_cnt[d4.x], 1);
        int p1 = atomicAdd(&g_cnt[d4.y], 1);
        int p2 = atomicAdd(&g_cnt[d4.z], 1);
        int p3 = atomicAdd(&g_cnt[d4.w], 1);
        if (p0 < CAP) g_col[d4.x * CAP + p0] = s4.x;
        if (p1 < CAP) g_col[d4.y * CAP + p1] = s4.y;
        if (p2 < CAP) g_col[d4.z * CAP + p2] = s4.z;
        if (p3 < CAP) g_col[d4.w * CAP + p3] = s4.w;
    } else {
        for (; i < e; ++i) {
            int d = dst[i];
            int p = atomicAdd(&g_cnt[d], 1);
            if (p < CAP) g_col[d * CAP + p] = src[i];
        }
    }
}

__global__ void dinv_kernel(int n) {
    int i = blockIdx.x * blockDim.x + threadIdx.x;
    if (i < n) g_dinv[i] = rsqrtf((float)(g_cnt[i] + 1));   // +1 self loop
}

// ---------------- tiled fp32 GEMM with f32x2 packed FMA ----------------
// out[n, * (stride OUTS)] = in[n, K (stride INS)] @ W[K, NOUT]
// OUTH=true  -> write fp16 to outh, ALL NP columns (pad cols are exact zeros).
// OUTH=false -> write fp32 to outf, guarded c < NOUT.
template<int K, int NOUT, int NP, int INS, int OUTS, bool SCALE, bool BIAS, bool OUTH>
__global__ void __launch_bounds__(256) gemm_kernel(const float* __restrict__ in,
                                                   const float* __restrict__ W,
                                                   const float* __restrict__ bias,
                                                   const float* __restrict__ dinv,
                                                   float* __restrict__ outf,
                                                   __half* __restrict__ outh, int n) {
    constexpr int BM = 128, BK = 32, NJ = NP / 32;
    __shared__ float xs[BK][BM + 4];
    __shared__ float ws[BK][NP];
    const int tid = threadIdx.x;
    const int tx = tid & 31, ty = tid >> 5;      // 8 warps, 16 rows each
    const int rbase = blockIdx.x * BM;

    unsigned long long acc2[8][NJ];              // row-pairs x cols
#pragma unroll
    for (int p = 0; p < 8; ++p)
#pragma unroll
        for (int j = 0; j < NJ; ++j) acc2[p][j] = 0ull;

    for (int kc = 0; kc < K; kc += BK) {
        // x tile: 128 rows x 32 k, 2 threads/row, stored transposed
        {
            int row  = tid >> 1;
            int q    = tid & 1;
            int grow = rbase + row;
#pragma unroll
            for (int h = 0; h < 4; ++h) {
                int c  = q * 16 + h * 4;
                int gk = kc + c;
                float4 xv = make_float4(0.f, 0.f, 0.f, 0.f);
                if (grow < n && gk < K)   // K % 4 == 0 so gk<K implies gk+3<K
                    xv = *(const float4*)(in + (size_t)grow * INS + gk);
                xs[c + 0][row] = xv.x;
                xs[c + 1][row] = xv.y;
                xs[c + 2][row] = xv.z;
                xs[c + 3][row] = xv.w;
            }
        }
        // W tile (zero padded)
        for (int i = tid; i < BK * NP; i += 256) {
            int kk = i / NP;
            int c  = i - kk * NP;
            int gkk = kc + kk;
            float w = 0.f;
            if (gkk < K && c < NOUT) w = W[gkk * NOUT + c];
            ws[kk][c] = w;
        }
        __syncthreads();
#pragma unroll
        for (int k = 0; k < BK; ++k) {
            const ulonglong2* pa = (const ulonglong2*)&xs[k][ty * 16];
            ulonglong2 v0 = pa[0], v1 = pa[1], v2 = pa[2], v3 = pa[3];
            unsigned long long a[8] = {v0.x, v0.y, v1.x, v1.y, v2.x, v2.y, v3.x, v3.y};
#pragma unroll
            for (int j = 0; j < NJ; ++j) {
                float w = ws[k][tx + 32 * j];
                unsigned long long wd = pack2(w, w);
#pragma unroll
                for (int p = 0; p < 8; ++p) ffma2(acc2[p][j], a[p], wd);
            }
        }
        __syncthreads();
    }
    // epilogue: unpack row pairs
#pragma unroll
    for (int p = 0; p < 8; ++p) {
        int r0 = rbase + ty * 16 + 2 * p;
        int r1 = r0 + 1;
        float dv0 = 1.f, dv1 = 1.f;
        if (SCALE) {
            if (r0 < n) dv0 = dinv[r0];
            if (r1 < n) dv1 = dinv[r1];
        }
#pragma unroll
        for (int j = 0; j < NJ; ++j) {
            int c = tx + 32 * j;
            float2 v = unpack2(acc2[p][j]);
            if (OUTH) {
                // pad columns carry exact zeros (ws zero-padded, no bias here)
                if (r0 < n) outh[(size_t)r0 * OUTS + c] = __float2half(v.x * dv0);
                if (r1 < n) outh[(size_t)r1 * OUTS + c] = __float2half(v.y * dv1);
            } else if (c < NOUT) {
                float b = BIAS ? bias[c] : 0.f;
                if (r0 < n) outf[(size_t)r0 * OUTS + c] = v.x * dv0 + b;
                if (r1 < n) outf[(size_t)r1 * OUTS + c] = v.y * dv1 + b;
            }
        }
    }
}

// ---------------- half-warp-per-node fp16 gather (layer 1) ----------------
// A rows: 128 halves = 256B, line-aligned -> 16 lanes x uint4, 2 nodes/warp.
// out[d] = relu( dinv[d] * ( A[d] + sum_src A[src] ) + bias ), fp32 stride 100.
__global__ void __launch_bounds__(256) agg100_kernel(const __half* __restrict__ A,
                                                     const float* __restrict__ bias,
                                                     float* __restrict__ out, int n) {
    const int gwarp = (blockIdx.x * blockDim.x + threadIdx.x) >> 5;
    const int lane  = threadIdx.x & 31;
    const int node  = gwarp * 2 + (lane >> 4);
    const int sub   = lane & 15;                  // 16B chunk index (8 halves)
    if (node >= n) return;
    const uint4* __restrict__ base = (const uint4*)A;   // 16 uint4 per row
    const size_t rowoff = (size_t)node * 16;

    float acc[8] = {0.f, 0.f, 0.f, 0.f, 0.f, 0.f, 0.f, 0.f};
    h8_add(base[rowoff + sub], acc);              // self loop term

    int deg = g_cnt[node]; if (deg > CAP) deg = CAP;
    const int4* __restrict__ colp = (const int4*)(g_col + node * CAP);
    const int nb4 = deg >> 2;
    for (int b = 0; b < nb4; ++b) {
        int4 i0 = colp[b];
        uint4 v0 = base[(size_t)i0.x * 16 + sub];
        uint4 v1 = base[(size_t)i0.y * 16 + sub];
        uint4 v2 = base[(size_t)i0.z * 16 + sub];
        uint4 v3 = base[(size_t)i0.w * 16 + sub];
        h8_add(v0, acc); h8_add(v1, acc); h8_add(v2, acc); h8_add(v3, acc);
    }
    for (int e = nb4 * 4; e < deg; ++e) {
        int s = g_col[node * CAP + e];
        h8_add(base[(size_t)s * 16 + sub], acc);
    }
    // epilogue: cols c0..c0+7 ; only c<100 stored
    const float dv = g_dinv[node];
    const int c0 = sub * 8;
    float* op = out + (size_t)node * F_HID + c0;
#pragma unroll
    for (int q = 0; q < 8; ++q) {
        int c = c0 + q;
        if (c < F_HID)
            op[q] = fmaxf(fmaf(acc[q], dv, bias[c]), 0.f);
    }
}

// ---------------- quarter-warp-per-node fp16 gather (layer 2) ----------------
// A rows: 64 halves = 128B = one cache line. 8 lanes x uint4, 4 nodes/warp.
__global__ void __launch_bounds__(256) agg64_kernel(const __half* __restrict__ A,
                                                    const float* __restrict__ bias,
                                                    float* __restrict__ out, int n) {
    const int gwarp = (blockIdx.x * blockDim.x + threadIdx.x) >> 5;
    const int lane  = threadIdx.x & 31;
    const int node  = gwarp * 4 + (lane >> 3);
    const int sub   = lane & 7;                   // 16B chunk (8 halves)
    if (node >= n) return;
    const uint4* __restrict__ base = (const uint4*)A;   // 8 uint4 per row
    const size_t rowoff = (size_t)node * 8;

    float acc[8] = {0.f, 0.f, 0.f, 0.f, 0.f, 0.f, 0.f, 0.f};
    h8_add(base[rowoff + sub], acc);              // self loop term

    int deg = g_cnt[node]; if (deg > CAP) deg = CAP;
    const int4* __restrict__ colp = (const int4*)(g_col + node * CAP);
    const int nb4 = deg >> 2;
    for (int b = 0; b < nb4; ++b) {
        int4 i0 = colp[b];
        uint4 v0 = base[(size_t)i0.x * 8 + sub];
        uint4 v1 = base[(size_t)i0.y * 8 + sub];
        uint4 v2 = base[(size_t)i0.z * 8 + sub];
        uint4 v3 = base[(size_t)i0.w * 8 + sub];
        h8_add(v0, acc); h8_add(v1, acc); h8_add(v2, acc); h8_add(v3, acc);
    }
    for (int e = nb4 * 4; e < deg; ++e) {
        int s = g_col[node * CAP + e];
        h8_add(base[(size_t)s * 8 + sub], acc);
    }
    const float dv = g_dinv[node];
    const int c0 = sub * 8;
    float* op = out + (size_t)node * F_EMB + c0;
    float4 r0, r1;
    r0.x = fmaxf(fmaf(acc[0], dv, bias[c0 + 0]), 0.f);
    r0.y = fmaxf(fmaf(acc[1], dv, bias[c0 + 1]), 0.f);
    r0.z = fmaxf(fmaf(acc[2], dv, bias[c0 + 2]), 0.f);
    r0.w = fmaxf(fmaf(acc[3], dv, bias[c0 + 3]), 0.f);
    r1.x = fmaxf(fmaf(acc[4], dv, bias[c0 + 4]), 0.f);
    r1.y = fmaxf(fmaf(acc[5], dv, bias[c0 + 5]), 0.f);
    r1.z = fmaxf(fmaf(acc[6], dv, bias[c0 + 6]), 0.f);
    r1.w = fmaxf(fmaf(acc[7], dv, bias[c0 + 7]), 0.f);
    *(float4*)(op + 0) = r0;
    *(float4*)(op + 4) = r1;
}

// ---------------- host launcher ----------------
extern "C" void kernel_launch(void* const* d_in, const int* in_sizes, int n_in,
                              void* d_out, int out_size) {
    const float* x    = (const float*)d_in[0];
    const int*   eidx = (const int*)d_in[1];
    const float* W1   = (const float*)d_in[2];
    const float* b1   = (const float*)d_in[3];
    const float* W2   = (const float*)d_in[4];
    const float* b2   = (const float*)d_in[5];
    const float* Wc   = (const float*)d_in[6];
    const float* bc   = (const float*)d_in[7];
    float* out = (float*)d_out;

    const int n = in_sizes[0] / F_IN;       // 50000
    const int e = in_sizes[1] / 2;          // 800000
    const int* src = eidx;
    const int* dst = eidx + e;

    // Device symbols must be resolved to device addresses before being passed
    // as kernel arguments (host shadow is ATS-dereferenceable on GB300 -> zeros).
    __half* gAh1; cudaGetSymbolAddress((void**)&gAh1, g_Ah1);
    __half* gAh2; cudaGetSymbolAddress((void**)&gAh2, g_Ah2);
    float*  gB1;  cudaGetSymbolAddress((void**)&gB1,  g_B1);
    float*  gB2;  cudaGetSymbolAddress((void**)&gB2,  g_B2);
    float*  gDinv;cudaGetSymbolAddress((void**)&gDinv,g_dinv);
    int*    gCnt; cudaGetSymbolAddress((void**)&gCnt, g_cnt);

    const int TB = 256;
    // slot-CSR build: memset cursor, bucket fill (ILP4), dinv from degree
    cudaMemsetAsync(gCnt, 0, n * sizeof(int));
    fill_kernel<<<((e + 3) / 4 + TB - 1) / TB, TB>>>(src, dst, e);
    dinv_kernel<<<(n + TB - 1) / TB, TB>>>(n);

    const int gemm_blocks   = (n + 127) / 128;
    const int agg100_blocks = (n + 15) / 16;     // 2 nodes per warp
    const int agg64_blocks  = (n + 31) / 32;     // 4 nodes per warp

    // layer 1: Ah1 = fp16( dinv * (x @ W1) ), padded to 128 halves
    gemm_kernel<F_IN, F_HID, 128, F_IN, PADH, true, false, true>
        <<<gemm_blocks, 256>>>(x, W1, nullptr, gDinv, nullptr, gAh1, n);
    // B1 = relu(dinv*(Ah1[d]+sum Ah1[src]) + b1)  fp32 stride 100
    agg100_kernel<<<agg100_blocks, 256>>>(gAh1, b1, gB1, n);

    // layer 2: Ah2 = fp16( dinv * (B1 @ W2) ), 64 halves (one line per row)
    gemm_kernel<F_HID, F_EMB, 64, F_HID, F_EMB, true, false, true>
        <<<gemm_blocks, 256>>>(gB1, W2, nullptr, gDinv, nullptr, gAh2, n);
    agg64_kernel<<<agg64_blocks, 256>>>(gAh2, b2, gB2, n);

    // classifier: out = B2 @ Wc + bc   (fp32)
    gemm_kernel<F_EMB, N_CLS, 64, F_EMB, N_CLS, false, true, false>
        <<<gemm_blocks, 256>>>(gB2, Wc, bc, nullptr, out, nullptr, n);
}